// round 5
// baseline (speedup 1.0000x reference)
#include <cuda_runtime.h>
#include <cstdint>

#define BATCH  16
#define TLEN   4096
#define DIM    512
#define CHUNK  32
#define MEMSZ  64
#define NSPLIT 8
#define DSLICE (DIM / NSPLIT)     // 64
#define NSTEP  (TLEN / CHUNK)     // 128
#define NBLK   (BATCH * NSPLIT)   // 128 blocks (all co-resident on GB300's 152 SMs)
#define NTHR   256
#define EPSF   1e-10f

// ---- cross-block scratch (static __device__, allocation-free) ----
__device__ float    g_plog[BATCH][NSPLIT][CHUNK][MEMSZ]; // partial logits (1 MB)
__device__ float    g_pdot[BATCH][NSPLIT][MEMSZ];        // partial dot(new_m, mem_m)
__device__ float    g_pmm [BATCH][NSPLIT][MEMSZ];        // partial ||mem_m||^2
__device__ float    g_pnn [BATCH][NSPLIT];               // partial ||new_m||^2
__device__ float    g_ent [BATCH];                       // per-batch entropy
__device__ unsigned g_ctr [2 * NSTEP + 8];               // one counter per barrier instance

// Software grid barrier: distinct counter per instance -> no reset/parity hazard.
// Counters are zeroed by a prologue kernel each launch (graph-replay safe).
__device__ __forceinline__ void gbar(unsigned* ctr, int tid) {
    __syncthreads();
    __threadfence();
    if (tid == 0) {
        unsigned v = atomicAdd(ctr, 1u) + 1u;
        if (v < NBLK) {
            while (*((volatile unsigned*)ctr) < NBLK) { }
        }
        __threadfence();
    }
    __syncthreads();
}

__global__ void zero_ctr_kernel() {
    int t = threadIdx.x;
    if (t < 2 * NSTEP + 8) g_ctr[t] = 0u;
}

__global__ void __launch_bounds__(NTHR, 1)
memk(const float* __restrict__ x, const float* __restrict__ mem_init,
     float* __restrict__ out)
{
    // Padded SMEM tiles (transposed-by-d layouts for conflict-free access)
    __shared__ float memS  [DSLICE][MEMSZ + 4]; // [d][m], stride 68 words
    __shared__ float chunkS[DSLICE][CHUNK + 2]; // [d][c], stride 34 words
    __shared__ float logS  [CHUNK][MEMSZ];      // reduced logits / probs
    __shared__ float newm  [DSLICE];
    __shared__ float score [MEMSZ];
    __shared__ float msS   [MEMSZ];             // m_score (replicated per block)
    __shared__ float mfS   [MEMSZ];             // m_freq
    __shared__ float simS  [MEMSZ];
    __shared__ float sEntMean;
    __shared__ int   sRepl, sMerge;

    const int tid  = threadIdx.x;
    const int bid  = blockIdx.x;
    const int b    = bid / NSPLIT;
    const int s    = bid % NSPLIT;
    const int d0   = s * DSLICE;
    const int lane = tid & 31;
    const int warp = tid >> 5;

    // init mem slice: mem_init[b][m][d0+d] -> memS[d][m]
    for (int i = tid; i < DSLICE * MEMSZ; i += NTHR) {
        int m = i >> 6;        // i / 64
        int d = i & 63;
        memS[d][m] = mem_init[((size_t)b * MEMSZ + m) * DIM + d0 + d];
    }
    for (int i = tid; i < MEMSZ; i += NTHR) { msS[i] = 0.0f; mfS[i] = 0.0f; }
    __syncthreads();

    const float scale = 1.0f / sqrtf((float)DIM);
    const float thr   = 0.5f * log2f((float)MEMSZ + EPSF);  // = 3.0

    const int i_c = tid >> 4;  // 0..15 -> c pair base 2*i_c
    const int j_m = tid & 15;  // 0..15 -> m quad base 4*j_m

    for (int step = 0; step < NSTEP; ++step) {
        // ================= Phase 1 =================
        // load chunk slice transposed: x[b][step*C+c][d0+d] -> chunkS[d][c]
        {
            const float* xb = x + ((size_t)b * TLEN + (size_t)step * CHUNK) * DIM + d0;
            for (int q = tid; q < CHUNK * (DSLICE / 4); q += NTHR) {
                int c  = q >> 4;   // / 16
                int dq = q & 15;
                float4 v = *(const float4*)(xb + (size_t)c * DIM + dq * 4);
                chunkS[dq * 4 + 0][c] = v.x;
                chunkS[dq * 4 + 1][c] = v.y;
                chunkS[dq * 4 + 2][c] = v.z;
                chunkS[dq * 4 + 3][c] = v.w;
            }
        }
        __syncthreads();

        // partial logits: 2x4 register tile per thread over 64-deep d slice
        float a00 = 0, a01 = 0, a02 = 0, a03 = 0;
        float a10 = 0, a11 = 0, a12 = 0, a13 = 0;
        #pragma unroll 4
        for (int d = 0; d < DSLICE; ++d) {
            float2 av = *(const float2*)&chunkS[d][2 * i_c];
            float4 bv = *(const float4*)&memS[d][4 * j_m];
            a00 = fmaf(av.x, bv.x, a00);
            a01 = fmaf(av.x, bv.y, a01);
            a02 = fmaf(av.x, bv.z, a02);
            a03 = fmaf(av.x, bv.w, a03);
            a10 = fmaf(av.y, bv.x, a10);
            a11 = fmaf(av.y, bv.y, a11);
            a12 = fmaf(av.y, bv.z, a12);
            a13 = fmaf(av.y, bv.w, a13);
        }
        {
            float4 v0 = make_float4(a00, a01, a02, a03);
            float4 v1 = make_float4(a10, a11, a12, a13);
            __stcg((float4*)&g_plog[b][s][2 * i_c][4 * j_m],     v0);
            __stcg((float4*)&g_plog[b][s][2 * i_c + 1][4 * j_m], v1);
        }
        // new_m slice: max over the 32 chunk tokens, per d
        if (tid < DSLICE) {
            float mx = chunkS[tid][0];
            #pragma unroll
            for (int c = 1; c < CHUNK; ++c) mx = fmaxf(mx, chunkS[tid][c]);
            newm[tid] = mx;
        }
        __syncthreads();
        // sim partials (current mem, current new_m slice)
        if (tid < MEMSZ) {
            float pd = 0.0f, pm = 0.0f;
            #pragma unroll 4
            for (int d = 0; d < DSLICE; ++d) {
                float mv = memS[d][tid];
                pd = fmaf(newm[d], mv, pd);
                pm = fmaf(mv, mv, pm);
            }
            __stcg(&g_pdot[b][s][tid], pd);
            __stcg(&g_pmm [b][s][tid], pm);
        } else if (tid < MEMSZ + 32) {
            int l = tid - MEMSZ;
            float n0 = newm[l], n1 = newm[l + 32];
            float nn = n0 * n0 + n1 * n1;
            #pragma unroll
            for (int o = 16; o; o >>= 1) nn += __shfl_xor_sync(0xffffffffu, nn, o);
            if (l == 0) __stcg(&g_pnn[b][s], nn);
        }
        gbar(&g_ctr[2 * step], tid);

        // ================= Phase 2 (redundant per batch) =================
        // deterministic fixed-order reduction of partial logits
        for (int q = tid; q < CHUNK * (MEMSZ / 4); q += NTHR) {
            int c  = q >> 4;
            int mq = q & 15;
            float4 r = make_float4(0, 0, 0, 0);
            #pragma unroll
            for (int ss = 0; ss < NSPLIT; ++ss) {
                float4 t = __ldcg((const float4*)&g_plog[b][ss][c][mq * 4]);
                r.x += t.x; r.y += t.y; r.z += t.z; r.w += t.w;
            }
            *(float4*)&logS[c][4 * mq] = r;
        }
        __syncthreads();
        // row-wise softmax (warp per row group)
        for (int c = warp; c < CHUNK; c += (NTHR / 32)) {
            float v0 = logS[c][lane]      * scale;
            float v1 = logS[c][lane + 32] * scale;
            float mx = fmaxf(v0, v1);
            #pragma unroll
            for (int o = 16; o; o >>= 1) mx = fmaxf(mx, __shfl_xor_sync(0xffffffffu, mx, o));
            float e0 = __expf(v0 - mx), e1 = __expf(v1 - mx);
            float sm = e0 + e1;
            #pragma unroll
            for (int o = 16; o; o >>= 1) sm += __shfl_xor_sync(0xffffffffu, sm, o);
            float inv = 1.0f / sm;
            logS[c][lane]      = e0 * inv;
            logS[c][lane + 32] = e1 * inv;
        }
        __syncthreads();
        if (tid < MEMSZ) {
            float sc = 0.0f;
            #pragma unroll
            for (int c = 0; c < CHUNK; ++c) sc += logS[c][tid];
            score[tid] = sc * (1.0f / CHUNK);
        } else if (tid < 2 * MEMSZ) {
            int m = tid - MEMSZ;
            float pd = 0.0f, pm = 0.0f, nn = 0.0f;
            #pragma unroll
            for (int ss = 0; ss < NSPLIT; ++ss) {
                pd += __ldcg(&g_pdot[b][ss][m]);
                pm += __ldcg(&g_pmm [b][ss][m]);
                nn += __ldcg(&g_pnn [b][ss]);
            }
            simS[m] = pd / (sqrtf(nn + 1e-8f) * sqrtf(pm + 1e-8f));
        }
        __syncthreads();
        if (warp == 0) {
            // entropy_b = sum_m -log2(score+eps)*score
            float s0 = score[lane], s1 = score[lane + 32];
            float e = -(log2f(s0 + EPSF) * s0 + log2f(s1 + EPSF) * s1);
            #pragma unroll
            for (int o = 16; o; o >>= 1) e += __shfl_xor_sync(0xffffffffu, e, o);
            if (lane == 0 && s == 0) __stcg(&g_ent[b], e);
        } else if (warp == 1) {
            // argmin of (m_score+score)/(m_freq+1), first-min tie-break
            float r0 = (msS[lane]      + score[lane])      / (mfS[lane]      + 1.0f);
            float r1 = (msS[lane + 32] + score[lane + 32]) / (mfS[lane + 32] + 1.0f);
            float v; int idx;
            if (r1 < r0) { v = r1; idx = lane + 32; } else { v = r0; idx = lane; }
            #pragma unroll
            for (int o = 16; o; o >>= 1) {
                float ov = __shfl_xor_sync(0xffffffffu, v, o);
                int   oi = __shfl_xor_sync(0xffffffffu, idx, o);
                if (ov < v || (ov == v && oi < idx)) { v = ov; idx = oi; }
            }
            if (lane == 0) sRepl = idx;
        } else if (warp == 2) {
            // argmax of cosine sim, first-max tie-break
            float v0 = simS[lane], v1 = simS[lane + 32];
            float v; int idx;
            if (v1 > v0) { v = v1; idx = lane + 32; } else { v = v0; idx = lane; }
            #pragma unroll
            for (int o = 16; o; o >>= 1) {
                float ov = __shfl_xor_sync(0xffffffffu, v, o);
                int   oi = __shfl_xor_sync(0xffffffffu, idx, o);
                if (ov > v || (ov == v && oi < idx)) { v = ov; idx = oi; }
            }
            if (lane == 0) sMerge = idx;
        }
        gbar(&g_ctr[2 * step + 1], tid);

        // ================= Phase 3 =================
        if (tid == 0) {
            float em = 0.0f;
            #pragma unroll
            for (int bb = 0; bb < BATCH; ++bb) em += __ldcg(&g_ent[bb]);
            sEntMean = em * (1.0f / BATCH);
        }
        __syncthreads();
        if (sEntMean > thr) {
            // path 1: replace lowest-avg-score slot with new_m
            int rm = sRepl;
            if (tid < DSLICE) {
                memS[tid][rm] = newm[tid];
            } else if (tid < DSLICE + MEMSZ) {
                int m = tid - DSLICE;
                float sn = msS[m] + score[m];
                float fn = mfS[m] + 1.0f;
                if (m == rm) { sn = 0.0f; fn = 1.0f; }
                msS[m] = sn; mfS[m] = fn;
            }
        } else {
            // path 2: 0.3*old + 0.7*new merge into nearest slot
            int im = sMerge;
            if (tid < DSLICE) {
                float old = memS[tid][im];
                memS[tid][im] = old + (0.7f * newm[tid] - 0.7f * old);
            }
        }
        __syncthreads();
    }

    // write final mem slice
    for (int i = tid; i < MEMSZ * DSLICE; i += NTHR) {
        int m = i >> 6;
        int d = i & 63;
        out[((size_t)b * MEMSZ + m) * DIM + d0 + d] = memS[d][m];
    }
}

extern "C" void kernel_launch(void* const* d_in, const int* in_sizes, int n_in,
                              void* d_out, int out_size) {
    const float* x        = (const float*)d_in[0];
    const float* mem_init = (const float*)d_in[1];
    // safety: x (33.5M elems) is the larger input
    if (n_in >= 2 && in_sizes[0] < in_sizes[1]) {
        const float* t = x; x = mem_init; mem_init = t;
    }
    float* out = (float*)d_out;

    zero_ctr_kernel<<<1, 512>>>();
    memk<<<NBLK, NTHR>>>(x, mem_init, out);
}

// round 6
// speedup vs baseline: 1.0017x; 1.0017x over previous
#include <cuda_runtime.h>
#include <cstdint>

#define BATCH  16
#define TLEN   4096
#define DIM    512
#define CHUNK  32
#define MEMSZ  64
#define NSPLIT 8
#define DSLICE (DIM / NSPLIT)     // 64
#define NSTEP  (TLEN / CHUNK)     // 128
#define NBLK   (BATCH * NSPLIT)   // 128 blocks (all co-resident on GB300's 152 SMs)
#define NTHR   256
#define EPSF   1e-10f

// ---- cross-block scratch (static __device__, allocation-free) ----
__device__ float    g_plog[BATCH][NSPLIT][CHUNK][MEMSZ]; // partial logits (1 MB)
__device__ float    g_pdot[BATCH][NSPLIT][MEMSZ];        // partial dot(new_m, mem_m)
__device__ float    g_pmm [BATCH][NSPLIT][MEMSZ];        // partial ||mem_m||^2
__device__ float    g_pnn [BATCH][NSPLIT];               // partial ||new_m||^2
__device__ float    g_ent [BATCH];                       // per-batch entropy
__device__ unsigned g_ctr [2 * NSTEP + 8];               // one counter per barrier instance

// Software grid barrier: distinct counter per instance -> no reset/parity hazard.
// Counters are zeroed by a prologue kernel each launch (graph-replay safe).
__device__ __forceinline__ void gbar(unsigned* ctr, int tid) {
    __syncthreads();
    __threadfence();
    if (tid == 0) {
        unsigned v = atomicAdd(ctr, 1u) + 1u;
        if (v < NBLK) {
            while (*((volatile unsigned*)ctr) < NBLK) { }
        }
        __threadfence();
    }
    __syncthreads();
}

__global__ void zero_ctr_kernel() {
    int t = threadIdx.x;
    if (t < 2 * NSTEP + 8) g_ctr[t] = 0u;
}

__global__ void __launch_bounds__(NTHR, 1)
memk(const float* __restrict__ x, const float* __restrict__ mem_init,
     float* __restrict__ out)
{
    // Padded SMEM tiles (transposed-by-d layouts for conflict-free access)
    __shared__ float memS  [DSLICE][MEMSZ + 4]; // [d][m], stride 68 words
    __shared__ float chunkS[DSLICE][CHUNK + 2]; // [d][c], stride 34 words
    __shared__ float logS  [CHUNK][MEMSZ];      // reduced logits / probs
    __shared__ float newm  [DSLICE];
    __shared__ float score [MEMSZ];
    __shared__ float msS   [MEMSZ];             // m_score (replicated per block)
    __shared__ float mfS   [MEMSZ];             // m_freq
    __shared__ float simS  [MEMSZ];
    __shared__ float sEntMean;
    __shared__ int   sRepl, sMerge;

    const int tid  = threadIdx.x;
    const int bid  = blockIdx.x;
    const int b    = bid / NSPLIT;
    const int s    = bid % NSPLIT;
    const int d0   = s * DSLICE;
    const int lane = tid & 31;
    const int warp = tid >> 5;

    // init mem slice: mem_init[b][m][d0+d] -> memS[d][m]
    for (int i = tid; i < DSLICE * MEMSZ; i += NTHR) {
        int m = i >> 6;        // i / 64
        int d = i & 63;
        memS[d][m] = mem_init[((size_t)b * MEMSZ + m) * DIM + d0 + d];
    }
    for (int i = tid; i < MEMSZ; i += NTHR) { msS[i] = 0.0f; mfS[i] = 0.0f; }
    __syncthreads();

    const float scale = 1.0f / sqrtf((float)DIM);
    const float thr   = 0.5f * log2f((float)MEMSZ + EPSF);  // = 3.0

    const int i_c = tid >> 4;  // 0..15 -> c pair base 2*i_c
    const int j_m = tid & 15;  // 0..15 -> m quad base 4*j_m

    for (int step = 0; step < NSTEP; ++step) {
        // ================= Phase 1 =================
        // load chunk slice transposed: x[b][step*C+c][d0+d] -> chunkS[d][c]
        {
            const float* xb = x + ((size_t)b * TLEN + (size_t)step * CHUNK) * DIM + d0;
            for (int q = tid; q < CHUNK * (DSLICE / 4); q += NTHR) {
                int c  = q >> 4;   // / 16
                int dq = q & 15;
                float4 v = *(const float4*)(xb + (size_t)c * DIM + dq * 4);
                chunkS[dq * 4 + 0][c] = v.x;
                chunkS[dq * 4 + 1][c] = v.y;
                chunkS[dq * 4 + 2][c] = v.z;
                chunkS[dq * 4 + 3][c] = v.w;
            }
        }
        __syncthreads();

        // partial logits: 2x4 register tile per thread over 64-deep d slice
        float a00 = 0, a01 = 0, a02 = 0, a03 = 0;
        float a10 = 0, a11 = 0, a12 = 0, a13 = 0;
        #pragma unroll 4
        for (int d = 0; d < DSLICE; ++d) {
            float2 av = *(const float2*)&chunkS[d][2 * i_c];
            float4 bv = *(const float4*)&memS[d][4 * j_m];
            a00 = fmaf(av.x, bv.x, a00);
            a01 = fmaf(av.x, bv.y, a01);
            a02 = fmaf(av.x, bv.z, a02);
            a03 = fmaf(av.x, bv.w, a03);
            a10 = fmaf(av.y, bv.x, a10);
            a11 = fmaf(av.y, bv.y, a11);
            a12 = fmaf(av.y, bv.z, a12);
            a13 = fmaf(av.y, bv.w, a13);
        }
        {
            float4 v0 = make_float4(a00, a01, a02, a03);
            float4 v1 = make_float4(a10, a11, a12, a13);
            __stcg((float4*)&g_plog[b][s][2 * i_c][4 * j_m],     v0);
            __stcg((float4*)&g_plog[b][s][2 * i_c + 1][4 * j_m], v1);
        }
        // new_m slice: max over the 32 chunk tokens, per d
        if (tid < DSLICE) {
            float mx = chunkS[tid][0];
            #pragma unroll
            for (int c = 1; c < CHUNK; ++c) mx = fmaxf(mx, chunkS[tid][c]);
            newm[tid] = mx;
        }
        __syncthreads();
        // sim partials (current mem, current new_m slice)
        if (tid < MEMSZ) {
            float pd = 0.0f, pm = 0.0f;
            #pragma unroll 4
            for (int d = 0; d < DSLICE; ++d) {
                float mv = memS[d][tid];
                pd = fmaf(newm[d], mv, pd);
                pm = fmaf(mv, mv, pm);
            }
            __stcg(&g_pdot[b][s][tid], pd);
            __stcg(&g_pmm [b][s][tid], pm);
        } else if (tid < MEMSZ + 32) {
            int l = tid - MEMSZ;
            float n0 = newm[l], n1 = newm[l + 32];
            float nn = n0 * n0 + n1 * n1;
            #pragma unroll
            for (int o = 16; o; o >>= 1) nn += __shfl_xor_sync(0xffffffffu, nn, o);
            if (l == 0) __stcg(&g_pnn[b][s], nn);
        }
        gbar(&g_ctr[2 * step], tid);

        // ================= Phase 2 (redundant per batch) =================
        // deterministic fixed-order reduction of partial logits
        for (int q = tid; q < CHUNK * (MEMSZ / 4); q += NTHR) {
            int c  = q >> 4;
            int mq = q & 15;
            float4 r = make_float4(0, 0, 0, 0);
            #pragma unroll
            for (int ss = 0; ss < NSPLIT; ++ss) {
                float4 t = __ldcg((const float4*)&g_plog[b][ss][c][mq * 4]);
                r.x += t.x; r.y += t.y; r.z += t.z; r.w += t.w;
            }
            *(float4*)&logS[c][4 * mq] = r;
        }
        __syncthreads();
        // row-wise softmax (warp per row group)
        for (int c = warp; c < CHUNK; c += (NTHR / 32)) {
            float v0 = logS[c][lane]      * scale;
            float v1 = logS[c][lane + 32] * scale;
            float mx = fmaxf(v0, v1);
            #pragma unroll
            for (int o = 16; o; o >>= 1) mx = fmaxf(mx, __shfl_xor_sync(0xffffffffu, mx, o));
            float e0 = __expf(v0 - mx), e1 = __expf(v1 - mx);
            float sm = e0 + e1;
            #pragma unroll
            for (int o = 16; o; o >>= 1) sm += __shfl_xor_sync(0xffffffffu, sm, o);
            float inv = 1.0f / sm;
            logS[c][lane]      = e0 * inv;
            logS[c][lane + 32] = e1 * inv;
        }
        __syncthreads();
        if (tid < MEMSZ) {
            float sc = 0.0f;
            #pragma unroll
            for (int c = 0; c < CHUNK; ++c) sc += logS[c][tid];
            score[tid] = sc * (1.0f / CHUNK);
        } else if (tid < 2 * MEMSZ) {
            int m = tid - MEMSZ;
            float pd = 0.0f, pm = 0.0f, nn = 0.0f;
            #pragma unroll
            for (int ss = 0; ss < NSPLIT; ++ss) {
                pd += __ldcg(&g_pdot[b][ss][m]);
                pm += __ldcg(&g_pmm [b][ss][m]);
                nn += __ldcg(&g_pnn [b][ss]);
            }
            simS[m] = pd / (sqrtf(nn + 1e-8f) * sqrtf(pm + 1e-8f));
        }
        __syncthreads();
        if (warp == 0) {
            // entropy_b = sum_m -log2(score+eps)*score
            float s0 = score[lane], s1 = score[lane + 32];
            float e = -(log2f(s0 + EPSF) * s0 + log2f(s1 + EPSF) * s1);
            #pragma unroll
            for (int o = 16; o; o >>= 1) e += __shfl_xor_sync(0xffffffffu, e, o);
            if (lane == 0 && s == 0) __stcg(&g_ent[b], e);
        } else if (warp == 1) {
            // argmin of (m_score+score)/(m_freq+1), first-min tie-break
            float r0 = (msS[lane]      + score[lane])      / (mfS[lane]      + 1.0f);
            float r1 = (msS[lane + 32] + score[lane + 32]) / (mfS[lane + 32] + 1.0f);
            float v; int idx;
            if (r1 < r0) { v = r1; idx = lane + 32; } else { v = r0; idx = lane; }
            #pragma unroll
            for (int o = 16; o; o >>= 1) {
                float ov = __shfl_xor_sync(0xffffffffu, v, o);
                int   oi = __shfl_xor_sync(0xffffffffu, idx, o);
                if (ov < v || (ov == v && oi < idx)) { v = ov; idx = oi; }
            }
            if (lane == 0) sRepl = idx;
        } else if (warp == 2) {
            // argmax of cosine sim, first-max tie-break
            float v0 = simS[lane], v1 = simS[lane + 32];
            float v; int idx;
            if (v1 > v0) { v = v1; idx = lane + 32; } else { v = v0; idx = lane; }
            #pragma unroll
            for (int o = 16; o; o >>= 1) {
                float ov = __shfl_xor_sync(0xffffffffu, v, o);
                int   oi = __shfl_xor_sync(0xffffffffu, idx, o);
                if (ov > v || (ov == v && oi < idx)) { v = ov; idx = oi; }
            }
            if (lane == 0) sMerge = idx;
        }
        gbar(&g_ctr[2 * step + 1], tid);

        // ================= Phase 3 =================
        if (tid == 0) {
            float em = 0.0f;
            #pragma unroll
            for (int bb = 0; bb < BATCH; ++bb) em += __ldcg(&g_ent[bb]);
            sEntMean = em * (1.0f / BATCH);
        }
        __syncthreads();
        if (sEntMean > thr) {
            // path 1: replace lowest-avg-score slot with new_m
            int rm = sRepl;
            if (tid < DSLICE) {
                memS[tid][rm] = newm[tid];
            } else if (tid < DSLICE + MEMSZ) {
                int m = tid - DSLICE;
                float sn = msS[m] + score[m];
                float fn = mfS[m] + 1.0f;
                if (m == rm) { sn = 0.0f; fn = 1.0f; }
                msS[m] = sn; mfS[m] = fn;
            }
        } else {
            // path 2: 0.3*old + 0.7*new merge into nearest slot
            int im = sMerge;
            if (tid < DSLICE) {
                float old = memS[tid][im];
                memS[tid][im] = old + (0.7f * newm[tid] - 0.7f * old);
            }
        }
        __syncthreads();
    }

    // write final mem slice
    for (int i = tid; i < MEMSZ * DSLICE; i += NTHR) {
        int m = i >> 6;
        int d = i & 63;
        out[((size_t)b * MEMSZ + m) * DIM + d0 + d] = memS[d][m];
    }
}

extern "C" void kernel_launch(void* const* d_in, const int* in_sizes, int n_in,
                              void* d_out, int out_size) {
    const float* x        = (const float*)d_in[0];
    const float* mem_init = (const float*)d_in[1];
    // safety: x (33.5M elems) is the larger input
    if (n_in >= 2 && in_sizes[0] < in_sizes[1]) {
        const float* t = x; x = mem_init; mem_init = t;
    }
    float* out = (float*)d_out;

    zero_ctr_kernel<<<1, 512>>>();
    memk<<<NBLK, NTHR>>>(x, mem_init, out);
}